// round 1
// baseline (speedup 1.0000x reference)
#include <cuda_runtime.h>
#include <math.h>

#define B_ 8
#define T_ 4096
#define D_ 768
#define DI_ 1536
#define M_ (B_*T_)          // 32768 rows
#define CB_ 256             // big chunk
#define NSTEP_ (T_/CB_)     // 16

// ---------------- scratch (device globals; no runtime allocation) ----------
__device__ float g_rms[M_];
__device__ float g_val[(size_t)M_*DI_];     // pre-conv val projection
__device__ float g_gate[(size_t)M_*DI_];    // silu(gate proj), then reused as h
__device__ float g_out[(size_t)M_*D_];      // conv_mix output
__device__ float g_v[(size_t)M_*D_];        // write projection
__device__ float g_reads[(size_t)M_*D_];
__device__ float g_W[2][(size_t)B_*D_*D_];  // double-buffered state
__device__ float g_P[(size_t)B_*CB_*CB_];   // (S o M) scratch
__device__ float g_consts[2];               // [0]=log(gamma), [1]=alpha

// ---------------- small kernels --------------------------------------------
__global__ void k_consts(const float* __restrict__ decay,
                         const float* __restrict__ log_alpha) {
    float g = 1.f / (1.f + expf(-decay[0]));
    g_consts[0] = logf(g);
    g_consts[1] = expf(log_alpha[0]);
}

__global__ void k_zeroW() {
    size_t i = (size_t)blockIdx.x * blockDim.x + threadIdx.x;
    if (i < (size_t)B_ * D_ * D_) g_W[0][i] = 0.f;
}

// one warp per row: inv_rms = rsqrt(mean(x^2)+eps)
__global__ void k_rms(const float* __restrict__ x) {
    int warp = threadIdx.x >> 5, lane = threadIdx.x & 31;
    int row = blockIdx.x * 8 + warp;
    const float* p = x + (size_t)row * D_;
    float s = 0.f;
    #pragma unroll
    for (int i = lane; i < D_; i += 32) { float v = p[i]; s += v * v; }
    #pragma unroll
    for (int o = 16; o; o >>= 1) s += __shfl_xor_sync(0xffffffffu, s, o);
    if (lane == 0) g_rms[row] = rsqrtf(s * (1.f / D_) + 1e-5f);
}

// depthwise causal conv(4) + silu, times pre-silu'd gate; writes into g_gate
__global__ void k_conv(const float* __restrict__ cw, const float* __restrict__ cb) {
    int e = blockIdx.x * 256 + threadIdx.x;   // 0..1535
    int t = blockIdx.y, b = blockIdx.z;
    size_t base = ((size_t)b * T_ + t) * DI_ + e;
    float w0 = cw[e*4+0], w1 = cw[e*4+1], w2 = cw[e*4+2], w3 = cw[e*4+3];
    float v = cb[e];
    if (t >= 3) v += g_val[base - 3*(size_t)DI_] * w0;
    if (t >= 2) v += g_val[base - 2*(size_t)DI_] * w1;
    if (t >= 1) v += g_val[base - 1*(size_t)DI_] * w2;
    v += g_val[base] * w3;
    float s = v / (1.f + __expf(-v));         // silu
    g_gate[base] = s * g_gate[base];          // gate already silu'd
}

// ---------------- big TN GEMM: C[m,n] = f(sum_k A[m,k]*B[n,k]) --------------
// 128x128 tile, BK=16, 256 threads, 8x8 per thread
// mode 0: C=acc ; 1: C=silu(acc) ; 2: C=add1+add2+alpha*acc
__global__ __launch_bounds__(256) void k_gemm128(
    const float* __restrict__ A, const float* __restrict__ Bm,
    float* __restrict__ C, int N, int K,
    const float* __restrict__ rsA, const float* __restrict__ csA,
    int mode, const float* __restrict__ add1, const float* __restrict__ add2)
{
    __shared__ float As[16][132];
    __shared__ float Bs[16][132];
    int tid = threadIdx.x;
    int m0 = blockIdx.y * 128, n0 = blockIdx.x * 128;
    int r = tid >> 2, kc = (tid & 3) << 2;
    int tx = tid & 15, ty = tid >> 4;
    float acc[8][8];
    #pragma unroll
    for (int i = 0; i < 8; i++)
        #pragma unroll
        for (int j = 0; j < 8; j++) acc[i][j] = 0.f;

    for (int k0 = 0; k0 < K; k0 += 16) {
        float4 cs = make_float4(1.f,1.f,1.f,1.f);
        if (csA) cs = *(const float4*)(csA + k0 + kc);
        #pragma unroll
        for (int it = 0; it < 2; it++) {
            int rr = r + it * 64;
            float4 av = *(const float4*)(A + (size_t)(m0 + rr) * K + k0 + kc);
            float sc = rsA ? rsA[m0 + rr] : 1.f;
            As[kc+0][rr] = av.x * sc * cs.x;
            As[kc+1][rr] = av.y * sc * cs.y;
            As[kc+2][rr] = av.z * sc * cs.z;
            As[kc+3][rr] = av.w * sc * cs.w;
            float4 bv = *(const float4*)(Bm + (size_t)(n0 + rr) * K + k0 + kc);
            Bs[kc+0][rr] = bv.x;
            Bs[kc+1][rr] = bv.y;
            Bs[kc+2][rr] = bv.z;
            Bs[kc+3][rr] = bv.w;
        }
        __syncthreads();
        #pragma unroll
        for (int kk = 0; kk < 16; kk++) {
            float4 a0 = *(const float4*)&As[kk][ty*8];
            float4 a1 = *(const float4*)&As[kk][ty*8+4];
            float4 b0 = *(const float4*)&Bs[kk][tx*8];
            float4 b1 = *(const float4*)&Bs[kk][tx*8+4];
            float a[8] = {a0.x,a0.y,a0.z,a0.w,a1.x,a1.y,a1.z,a1.w};
            float b[8] = {b0.x,b0.y,b0.z,b0.w,b1.x,b1.y,b1.z,b1.w};
            #pragma unroll
            for (int i = 0; i < 8; i++)
                #pragma unroll
                for (int j = 0; j < 8; j++) acc[i][j] += a[i] * b[j];
        }
        __syncthreads();
    }
    float alpha = (mode == 2) ? g_consts[1] : 0.f;
    #pragma unroll
    for (int i = 0; i < 8; i++) {
        size_t row = (size_t)(m0 + ty*8 + i) * N;
        #pragma unroll
        for (int j = 0; j < 8; j += 4) {
            int n = n0 + tx*8 + j;
            float4 v = make_float4(acc[i][j], acc[i][j+1], acc[i][j+2], acc[i][j+3]);
            if (mode == 1) {
                v.x = v.x / (1.f + __expf(-v.x));
                v.y = v.y / (1.f + __expf(-v.y));
                v.z = v.z / (1.f + __expf(-v.z));
                v.w = v.w / (1.f + __expf(-v.w));
            } else if (mode == 2) {
                float4 a1 = *(const float4*)(add1 + row + n);
                float4 a2 = *(const float4*)(add2 + row + n);
                v.x = a1.x + a2.x + alpha * v.x;
                v.y = a1.y + a2.y + alpha * v.y;
                v.z = a1.z + a2.z + alpha * v.z;
                v.w = a1.w + a2.w + alpha * v.w;
            }
            *(float4*)(C + row + n) = v;
        }
    }
}

// ---------------- scan kernels (64x64 tiles, 4x4 per thread) ----------------
// P[b][i][j] = (i>j) ? (r_i . k_j) * gamma^(i-1-j) : 0 ;  k_j = out[t0+j-1]
__global__ __launch_bounds__(256) void k_pchunk(int t0) {
    int b = blockIdx.z;
    const float* A = g_out + ((size_t)b * T_ + t0) * D_;   // r rows
    __shared__ float As[16][68], Bs[16][68];
    int tid = threadIdx.x;
    int r = tid >> 2, kc = (tid & 3) << 2;
    int tx = tid & 15, ty = tid >> 4;
    int m0 = blockIdx.y * 64, n0 = blockIdx.x * 64;
    float acc[4][4] = {};
    for (int k0 = 0; k0 < D_; k0 += 16) {
        float4 av = *(const float4*)(A + (size_t)(m0 + r) * D_ + k0 + kc);
        As[kc+0][r] = av.x; As[kc+1][r] = av.y; As[kc+2][r] = av.z; As[kc+3][r] = av.w;
        int tok = t0 + n0 + r - 1;
        float4 bv = make_float4(0.f,0.f,0.f,0.f);
        if (tok >= 0)
            bv = *(const float4*)(g_out + ((size_t)b * T_ + tok) * D_ + k0 + kc);
        Bs[kc+0][r] = bv.x; Bs[kc+1][r] = bv.y; Bs[kc+2][r] = bv.z; Bs[kc+3][r] = bv.w;
        __syncthreads();
        #pragma unroll
        for (int kk = 0; kk < 16; kk++) {
            float4 a = *(const float4*)&As[kk][ty*4];
            float4 bq = *(const float4*)&Bs[kk][tx*4];
            float av4[4] = {a.x,a.y,a.z,a.w}, bv4[4] = {bq.x,bq.y,bq.z,bq.w};
            #pragma unroll
            for (int i = 0; i < 4; i++)
                #pragma unroll
                for (int j = 0; j < 4; j++) acc[i][j] += av4[i] * bv4[j];
        }
        __syncthreads();
    }
    float lg = g_consts[0];
    float* P = g_P + (size_t)b * CB_ * CB_;
    #pragma unroll
    for (int i = 0; i < 4; i++) {
        int ii = m0 + ty*4 + i;
        #pragma unroll
        for (int j = 0; j < 4; j++) {
            int jj = n0 + tx*4 + j;
            P[(size_t)ii * CB_ + jj] =
                (ii > jj) ? acc[i][j] * __expf((float)(ii - 1 - jj) * lg) : 0.f;
        }
    }
}

// Wn[b][d][e] = gamma^CB * Wc[b][d][e] + sum_i gamma^(CB-1-i) v[i,d] k[i,e]
__global__ __launch_bounds__(256) void k_wupdate(int t0,
        const float* __restrict__ Wc, float* __restrict__ Wn) {
    int b = blockIdx.z;
    const float* Av = g_v + ((size_t)b * T_ + t0) * D_;
    __shared__ float As[16][68], Bs[16][68];
    int tid = threadIdx.x;
    int ki = tid >> 4, cc = (tid & 15) << 2;
    int tx = tid & 15, ty = tid >> 4;
    int m0 = blockIdx.y * 64, n0 = blockIdx.x * 64;
    float lg = g_consts[0];
    float acc[4][4] = {};
    for (int k0 = 0; k0 < CB_; k0 += 16) {
        int i = k0 + ki;
        float gw = __expf((float)(CB_ - 1 - i) * lg);
        float4 av = *(const float4*)(Av + (size_t)i * D_ + m0 + cc);
        As[ki][cc+0] = av.x * gw; As[ki][cc+1] = av.y * gw;
        As[ki][cc+2] = av.z * gw; As[ki][cc+3] = av.w * gw;
        int tok = t0 + i - 1;
        float4 bv = make_float4(0.f,0.f,0.f,0.f);
        if (tok >= 0)
            bv = *(const float4*)(g_out + ((size_t)b * T_ + tok) * D_ + n0 + cc);
        Bs[ki][cc+0] = bv.x; Bs[ki][cc+1] = bv.y; Bs[ki][cc+2] = bv.z; Bs[ki][cc+3] = bv.w;
        __syncthreads();
        #pragma unroll
        for (int kk = 0; kk < 16; kk++) {
            float4 a = *(const float4*)&As[kk][ty*4];
            float4 bq = *(const float4*)&Bs[kk][tx*4];
            float av4[4] = {a.x,a.y,a.z,a.w}, bv4[4] = {bq.x,bq.y,bq.z,bq.w};
            #pragma unroll
            for (int i2 = 0; i2 < 4; i2++)
                #pragma unroll
                for (int j = 0; j < 4; j++) acc[i2][j] += av4[i2] * bv4[j];
        }
        __syncthreads();
    }
    float gC = __expf((float)CB_ * lg);
    size_t base = (size_t)b * D_ * D_;
    #pragma unroll
    for (int i = 0; i < 4; i++) {
        int d = m0 + ty*4 + i;
        #pragma unroll
        for (int j = 0; j < 4; j++) {
            int e = n0 + tx*4 + j;
            size_t idx = base + (size_t)d * D_ + e;
            Wn[idx] = gC * Wc[idx] + acc[i][j];
        }
    }
}

// reads[t0+i, d] = gamma^i * sum_e r[i,e] W[d,e]  +  sum_j P[i,j] v[j,d]
__global__ __launch_bounds__(256) void k_reads(int t0, const float* __restrict__ Wc) {
    int b = blockIdx.z;
    const float* A  = g_out + ((size_t)b * T_ + t0) * D_;
    const float* Wb = Wc + (size_t)b * D_ * D_;
    const float* P  = g_P + (size_t)b * CB_ * CB_;
    const float* Vv = g_v + ((size_t)b * T_ + t0) * D_;
    __shared__ float As[16][68], Bs[16][68];
    int tid = threadIdx.x;
    int r = tid >> 2, kc = (tid & 3) << 2;
    int ki = tid >> 4, cc = (tid & 15) << 2;
    int tx = tid & 15, ty = tid >> 4;
    int m0 = blockIdx.y * 64, n0 = blockIdx.x * 64;
    float acc[4][4] = {};
    // phase 1: inter = r @ W^T (contract over e, both K-contiguous)
    for (int k0 = 0; k0 < D_; k0 += 16) {
        float4 av = *(const float4*)(A + (size_t)(m0 + r) * D_ + k0 + kc);
        As[kc+0][r] = av.x; As[kc+1][r] = av.y; As[kc+2][r] = av.z; As[kc+3][r] = av.w;
        float4 bv = *(const float4*)(Wb + (size_t)(n0 + r) * D_ + k0 + kc);
        Bs[kc+0][r] = bv.x; Bs[kc+1][r] = bv.y; Bs[kc+2][r] = bv.z; Bs[kc+3][r] = bv.w;
        __syncthreads();
        #pragma unroll
        for (int kk = 0; kk < 16; kk++) {
            float4 a = *(const float4*)&As[kk][ty*4];
            float4 bq = *(const float4*)&Bs[kk][tx*4];
            float av4[4] = {a.x,a.y,a.z,a.w}, bv4[4] = {bq.x,bq.y,bq.z,bq.w};
            #pragma unroll
            for (int i = 0; i < 4; i++)
                #pragma unroll
                for (int j = 0; j < 4; j++) acc[i][j] += av4[i] * bv4[j];
        }
        __syncthreads();
    }
    float lg = g_consts[0];
    #pragma unroll
    for (int i = 0; i < 4; i++) {
        float sc = __expf((float)(m0 + ty*4 + i) * lg);
        #pragma unroll
        for (int j = 0; j < 4; j++) acc[i][j] *= sc;
    }
    // phase 2: intra = P @ v (contract over j; P K-contig, v row-major over d)
    for (int k0 = 0; k0 < CB_; k0 += 16) {
        float4 av = *(const float4*)(P + (size_t)(m0 + r) * CB_ + k0 + kc);
        As[kc+0][r] = av.x; As[kc+1][r] = av.y; As[kc+2][r] = av.z; As[kc+3][r] = av.w;
        float4 bv = *(const float4*)(Vv + (size_t)(k0 + ki) * D_ + n0 + cc);
        Bs[ki][cc+0] = bv.x; Bs[ki][cc+1] = bv.y; Bs[ki][cc+2] = bv.z; Bs[ki][cc+3] = bv.w;
        __syncthreads();
        #pragma unroll
        for (int kk = 0; kk < 16; kk++) {
            float4 a = *(const float4*)&As[kk][ty*4];
            float4 bq = *(const float4*)&Bs[kk][tx*4];
            float av4[4] = {a.x,a.y,a.z,a.w}, bv4[4] = {bq.x,bq.y,bq.z,bq.w};
            #pragma unroll
            for (int i = 0; i < 4; i++)
                #pragma unroll
                for (int j = 0; j < 4; j++) acc[i][j] += av4[i] * bv4[j];
        }
        __syncthreads();
    }
    #pragma unroll
    for (int i = 0; i < 4; i++) {
        size_t row = ((size_t)b * T_ + t0 + m0 + ty*4 + i) * D_;
        #pragma unroll
        for (int j = 0; j < 4; j++)
            g_reads[row + n0 + tx*4 + j] = acc[i][j];
    }
}

// ---------------- launch ----------------------------------------------------
extern "C" void kernel_launch(void* const* d_in, const int* in_sizes, int n_in,
                              void* d_out, int out_size) {
    const float* x         = (const float*)d_in[0];
    const float* norm_w    = (const float*)d_in[1];
    const float* proj_w    = (const float*)d_in[2];
    const float* gate_w    = (const float*)d_in[3];
    const float* conv_w    = (const float*)d_in[4];
    const float* conv_b    = (const float*)d_in[5];
    const float* out_proj  = (const float*)d_in[6];
    const float* write_w   = (const float*)d_in[7];
    const float* read_w    = (const float*)d_in[8];
    const float* decay     = (const float*)d_in[9];
    const float* log_alpha = (const float*)d_in[10];
    float* out = (float*)d_out;

    float *p_rms, *p_val, *p_gate, *p_out, *p_v, *p_reads, *p_W;
    cudaGetSymbolAddress((void**)&p_rms,   g_rms);
    cudaGetSymbolAddress((void**)&p_val,   g_val);
    cudaGetSymbolAddress((void**)&p_gate,  g_gate);
    cudaGetSymbolAddress((void**)&p_out,   g_out);
    cudaGetSymbolAddress((void**)&p_v,     g_v);
    cudaGetSymbolAddress((void**)&p_reads, g_reads);
    cudaGetSymbolAddress((void**)&p_W,     g_W);
    float* p_W0 = p_W;
    float* p_W1 = p_W + (size_t)B_ * D_ * D_;

    k_consts<<<1, 1>>>(decay, log_alpha);
    k_rms<<<M_/8, 256>>>(x);

    // val = Xn @ proj^T ; gate = silu(Xn @ gate^T)
    k_gemm128<<<dim3(DI_/128, M_/128), 256>>>(x, proj_w, p_val, DI_, D_,
                                              p_rms, norm_w, 0, nullptr, nullptr);
    k_gemm128<<<dim3(DI_/128, M_/128), 256>>>(x, gate_w, p_gate, DI_, D_,
                                              p_rms, norm_w, 1, nullptr, nullptr);
    // h = silu(conv(val)+b) * gate   (into g_gate)
    k_conv<<<dim3(DI_/256, T_, B_), 256>>>(conv_w, conv_b);
    // out = h @ out_proj^T
    k_gemm128<<<dim3(D_/128, M_/128), 256>>>(p_gate, out_proj, p_out, D_, DI_,
                                             nullptr, nullptr, 0, nullptr, nullptr);
    // v = out @ write^T
    k_gemm128<<<dim3(D_/128, M_/128), 256>>>(p_out, write_w, p_v, D_, D_,
                                             nullptr, nullptr, 0, nullptr, nullptr);

    // chunked decay-linear-attention scan
    k_zeroW<<<(int)(((size_t)B_*D_*D_ + 1023) / 1024), 1024>>>();
    const float* Wc = p_W0;
    float* Wn = p_W1;
    for (int s = 0; s < NSTEP_; s++) {
        int t0 = s * CB_;
        k_pchunk <<<dim3(CB_/64, CB_/64, B_), 256>>>(t0);
        k_wupdate<<<dim3(D_/64,  D_/64,  B_), 256>>>(t0, Wc, Wn);
        k_reads  <<<dim3(D_/64,  CB_/64, B_), 256>>>(t0, Wc);
        float* tmp = (float*)Wc; Wc = Wn; Wn = tmp;
    }

    // final: y = x + out + alpha * (reads @ read^T)
    k_gemm128<<<dim3(D_/128, M_/128), 256>>>(p_reads, read_w, out, D_, D_,
                                             nullptr, nullptr, 2, x, p_out);
}

// round 2
// speedup vs baseline: 2.6087x; 2.6087x over previous
#include <cuda_runtime.h>
#include <math.h>
#include <stdint.h>

#define B_ 8
#define T_ 4096
#define D_ 768
#define DI_ 1536
#define M_ (B_*T_)          // 32768 rows
#define CB_ 256             // big chunk
#define NSTEP_ (T_/CB_)     // 16

// ---------------- scratch (device globals; no runtime allocation) ----------
__device__ float g_rms[M_];
__device__ float g_val[(size_t)M_*DI_];     // pre-conv val projection
__device__ float g_gate[(size_t)M_*DI_];    // silu(gate proj), then reused as h
__device__ float g_out[(size_t)M_*D_];      // conv_mix output
__device__ float g_v[(size_t)M_*D_];        // write projection
__device__ float g_reads[(size_t)M_*D_];
__device__ float g_W[2][(size_t)B_*D_*D_];  // double-buffered state
__device__ float g_P[(size_t)B_*CB_*CB_];   // (S o M) scratch
__device__ float g_consts[2];               // [0]=log(gamma), [1]=alpha

// ---------------- helpers ---------------------------------------------------
__device__ __forceinline__ uint32_t f2tf(float f) {
    uint32_t u;
    asm("cvt.rna.tf32.f32 %0, %1;" : "=r"(u) : "f"(f));
    return u;
}

__device__ __forceinline__ void mma8(float* c, const uint32_t* a, const uint32_t* b) {
    asm volatile(
        "mma.sync.aligned.m16n8k8.row.col.f32.tf32.tf32.f32 "
        "{%0,%1,%2,%3}, {%4,%5,%6,%7}, {%8,%9}, {%0,%1,%2,%3};"
        : "+f"(c[0]), "+f"(c[1]), "+f"(c[2]), "+f"(c[3])
        : "r"(a[0]), "r"(a[1]), "r"(a[2]), "r"(a[3]), "r"(b[0]), "r"(b[1]));
}

// 128x128 block, 8 warps as 4(m) x 2(n), warp tile 32x64.
// As/Bs: [16][136] tf32, k-major.
__device__ __forceinline__ void mma_block(
    const uint32_t (*As)[136], const uint32_t (*Bs)[136],
    float acc[2][8][4], int warp_m, int warp_n, int quad, int tq)
{
    #pragma unroll
    for (int ks = 0; ks < 2; ks++) {
        int kb = ks * 8;
        uint32_t af[2][4];
        #pragma unroll
        for (int mt = 0; mt < 2; mt++) {
            int m = warp_m * 32 + mt * 16 + quad;
            af[mt][0] = As[kb + tq][m];
            af[mt][1] = As[kb + tq][m + 8];
            af[mt][2] = As[kb + tq + 4][m];
            af[mt][3] = As[kb + tq + 4][m + 8];
        }
        #pragma unroll
        for (int nt = 0; nt < 8; nt++) {
            uint32_t bf[2];
            int n = warp_n * 64 + nt * 8 + quad;
            bf[0] = Bs[kb + tq][n];
            bf[1] = Bs[kb + tq + 4][n];
            #pragma unroll
            for (int mt = 0; mt < 2; mt++) mma8(acc[mt][nt], af[mt], bf);
        }
    }
}

// ---------------- small kernels --------------------------------------------
__global__ void k_consts(const float* __restrict__ decay,
                         const float* __restrict__ log_alpha) {
    float g = 1.f / (1.f + expf(-decay[0]));
    g_consts[0] = logf(g);
    g_consts[1] = expf(log_alpha[0]);
}

__global__ void k_zeroW() {
    size_t i = (size_t)blockIdx.x * blockDim.x + threadIdx.x;
    if (i < (size_t)B_ * D_ * D_) g_W[0][i] = 0.f;
}

__global__ void k_rms(const float* __restrict__ x) {
    int warp = threadIdx.x >> 5, lane = threadIdx.x & 31;
    int row = blockIdx.x * 8 + warp;
    const float* p = x + (size_t)row * D_;
    float s = 0.f;
    #pragma unroll
    for (int i = lane; i < D_; i += 32) { float v = p[i]; s += v * v; }
    #pragma unroll
    for (int o = 16; o; o >>= 1) s += __shfl_xor_sync(0xffffffffu, s, o);
    if (lane == 0) g_rms[row] = rsqrtf(s * (1.f / D_) + 1e-5f);
}

__global__ void k_conv(const float* __restrict__ cw, const float* __restrict__ cb) {
    int e = blockIdx.x * 256 + threadIdx.x;
    int t = blockIdx.y, b = blockIdx.z;
    size_t base = ((size_t)b * T_ + t) * DI_ + e;
    float w0 = cw[e*4+0], w1 = cw[e*4+1], w2 = cw[e*4+2], w3 = cw[e*4+3];
    float v = cb[e];
    if (t >= 3) v += g_val[base - 3*(size_t)DI_] * w0;
    if (t >= 2) v += g_val[base - 2*(size_t)DI_] * w1;
    if (t >= 1) v += g_val[base - 1*(size_t)DI_] * w2;
    v += g_val[base] * w3;
    float s = v / (1.f + __expf(-v));
    g_gate[base] = s * g_gate[base];
}

// ---------------- big TN GEMM (tf32 tensor cores) ---------------------------
// C[m,n] = f(sum_k A[m,k]*B[n,k]); mode 0: C=acc ; 1: silu(acc) ; 2: add1+add2+alpha*acc
__global__ __launch_bounds__(256) void k_gemm128(
    const float* __restrict__ A, const float* __restrict__ Bm,
    float* __restrict__ C, int N, int K,
    const float* __restrict__ rsA, const float* __restrict__ csA,
    int mode, const float* __restrict__ add1, const float* __restrict__ add2)
{
    __shared__ uint32_t As[16][136];
    __shared__ uint32_t Bs[16][136];
    int tid = threadIdx.x;
    int m0 = blockIdx.y * 128, n0 = blockIdx.x * 128;
    int warp = tid >> 5, lane = tid & 31;
    int warp_m = warp >> 1, warp_n = warp & 1;
    int quad = lane >> 2, tq = lane & 3;
    int r = tid >> 2, kc = (tid & 3) << 2;
    float acc[2][8][4] = {};

    for (int k0 = 0; k0 < K; k0 += 16) {
        float4 cs = make_float4(1.f, 1.f, 1.f, 1.f);
        if (csA) cs = *(const float4*)(csA + k0 + kc);
        #pragma unroll
        for (int it = 0; it < 2; it++) {
            int rr = r + it * 64;
            float4 av = *(const float4*)(A + (size_t)(m0 + rr) * K + k0 + kc);
            float sc = rsA ? rsA[m0 + rr] : 1.f;
            As[kc+0][rr] = f2tf(av.x * sc * cs.x);
            As[kc+1][rr] = f2tf(av.y * sc * cs.y);
            As[kc+2][rr] = f2tf(av.z * sc * cs.z);
            As[kc+3][rr] = f2tf(av.w * sc * cs.w);
            float4 bv = *(const float4*)(Bm + (size_t)(n0 + rr) * K + k0 + kc);
            Bs[kc+0][rr] = f2tf(bv.x);
            Bs[kc+1][rr] = f2tf(bv.y);
            Bs[kc+2][rr] = f2tf(bv.z);
            Bs[kc+3][rr] = f2tf(bv.w);
        }
        __syncthreads();
        mma_block(As, Bs, acc, warp_m, warp_n, quad, tq);
        __syncthreads();
    }

    float alpha = (mode == 2) ? g_consts[1] : 0.f;
    #pragma unroll
    for (int mt = 0; mt < 2; mt++)
        #pragma unroll
        for (int h = 0; h < 2; h++) {
            int mi = m0 + warp_m * 32 + mt * 16 + quad + h * 8;
            size_t row = (size_t)mi * N;
            #pragma unroll
            for (int nt = 0; nt < 8; nt++) {
                int ni = n0 + warp_n * 64 + nt * 8 + tq * 2;
                float c0 = acc[mt][nt][h*2 + 0];
                float c1 = acc[mt][nt][h*2 + 1];
                if (mode == 1) {
                    c0 = c0 / (1.f + __expf(-c0));
                    c1 = c1 / (1.f + __expf(-c1));
                } else if (mode == 2) {
                    float2 a1 = *(const float2*)(add1 + row + ni);
                    float2 a2 = *(const float2*)(add2 + row + ni);
                    c0 = a1.x + a2.x + alpha * c0;
                    c1 = a1.y + a2.y + alpha * c1;
                }
                *(float2*)(C + row + ni) = make_float2(c0, c1);
            }
        }
}

// ---------------- scan kernels (tf32 tensor cores, 128x128 tiles) -----------
// P[b][i][j] = (i>j) ? (r_i . k_j) * gamma^(i-1-j) : 0 ;  k_j = out[t0+j-1]
__global__ __launch_bounds__(256) void k_pchunk(int t0) {
    int b = blockIdx.z;
    const float* A = g_out + ((size_t)b * T_ + t0) * D_;
    __shared__ uint32_t As[16][136];
    __shared__ uint32_t Bs[16][136];
    int tid = threadIdx.x;
    int m0 = blockIdx.y * 128, n0 = blockIdx.x * 128;
    int warp = tid >> 5, lane = tid & 31;
    int warp_m = warp >> 1, warp_n = warp & 1;
    int quad = lane >> 2, tq = lane & 3;
    int r = tid >> 2, kc = (tid & 3) << 2;
    float acc[2][8][4] = {};

    for (int k0 = 0; k0 < D_; k0 += 16) {
        #pragma unroll
        for (int it = 0; it < 2; it++) {
            int rr = r + it * 64;
            float4 av = *(const float4*)(A + (size_t)(m0 + rr) * D_ + k0 + kc);
            As[kc+0][rr] = f2tf(av.x); As[kc+1][rr] = f2tf(av.y);
            As[kc+2][rr] = f2tf(av.z); As[kc+3][rr] = f2tf(av.w);
            int tok = t0 + n0 + rr - 1;
            float4 bv = make_float4(0.f, 0.f, 0.f, 0.f);
            if (tok >= 0)
                bv = *(const float4*)(g_out + ((size_t)b * T_ + tok) * D_ + k0 + kc);
            Bs[kc+0][rr] = f2tf(bv.x); Bs[kc+1][rr] = f2tf(bv.y);
            Bs[kc+2][rr] = f2tf(bv.z); Bs[kc+3][rr] = f2tf(bv.w);
        }
        __syncthreads();
        mma_block(As, Bs, acc, warp_m, warp_n, quad, tq);
        __syncthreads();
    }

    float lg = g_consts[0];
    float* P = g_P + (size_t)b * CB_ * CB_;
    #pragma unroll
    for (int mt = 0; mt < 2; mt++)
        #pragma unroll
        for (int h = 0; h < 2; h++) {
            int ii = m0 + warp_m * 32 + mt * 16 + quad + h * 8;
            #pragma unroll
            for (int nt = 0; nt < 8; nt++) {
                int jj = n0 + warp_n * 64 + nt * 8 + tq * 2;
                float c0 = (ii > jj)     ? acc[mt][nt][h*2+0] * __expf((float)(ii-1-jj)   * lg) : 0.f;
                float c1 = (ii > jj + 1) ? acc[mt][nt][h*2+1] * __expf((float)(ii-2-jj)   * lg) : 0.f;
                *(float2*)(P + (size_t)ii * CB_ + jj) = make_float2(c0, c1);
            }
        }
}

// Wn[b][d][e] = gamma^CB * Wc[b][d][e] + sum_i gamma^(CB-1-i) v[i,d] k[i,e]
__global__ __launch_bounds__(256) void k_wupdate(int t0,
        const float* __restrict__ Wc, float* __restrict__ Wn) {
    int b = blockIdx.z;
    __shared__ uint32_t As[16][136];
    __shared__ uint32_t Bs[16][136];
    int tid = threadIdx.x;
    int m0 = blockIdx.y * 128, n0 = blockIdx.x * 128;
    int warp = tid >> 5, lane = tid & 31;
    int warp_m = warp >> 1, warp_n = warp & 1;
    int quad = lane >> 2, tq = lane & 3;
    int ki = tid >> 4, cc = (tid & 15) << 3;
    float lg = g_consts[0];
    float acc[2][8][4] = {};

    for (int k0 = 0; k0 < CB_; k0 += 16) {
        int i = k0 + ki;
        float gw = __expf((float)(CB_ - 1 - i) * lg);
        const float* arow = g_v + ((size_t)b * T_ + t0 + i) * D_ + m0 + cc;
        float4 a0 = *(const float4*)(arow);
        float4 a1 = *(const float4*)(arow + 4);
        As[ki][cc+0] = f2tf(a0.x * gw); As[ki][cc+1] = f2tf(a0.y * gw);
        As[ki][cc+2] = f2tf(a0.z * gw); As[ki][cc+3] = f2tf(a0.w * gw);
        As[ki][cc+4] = f2tf(a1.x * gw); As[ki][cc+5] = f2tf(a1.y * gw);
        As[ki][cc+6] = f2tf(a1.z * gw); As[ki][cc+7] = f2tf(a1.w * gw);
        int tok = t0 + i - 1;
        float4 b0 = make_float4(0.f,0.f,0.f,0.f), b1 = b0;
        if (tok >= 0) {
            const float* brow = g_out + ((size_t)b * T_ + tok) * D_ + n0 + cc;
            b0 = *(const float4*)(brow);
            b1 = *(const float4*)(brow + 4);
        }
        Bs[ki][cc+0] = f2tf(b0.x); Bs[ki][cc+1] = f2tf(b0.y);
        Bs[ki][cc+2] = f2tf(b0.z); Bs[ki][cc+3] = f2tf(b0.w);
        Bs[ki][cc+4] = f2tf(b1.x); Bs[ki][cc+5] = f2tf(b1.y);
        Bs[ki][cc+6] = f2tf(b1.z); Bs[ki][cc+7] = f2tf(b1.w);
        __syncthreads();
        mma_block(As, Bs, acc, warp_m, warp_n, quad, tq);
        __syncthreads();
    }

    float gC = __expf((float)CB_ * lg);
    size_t base = (size_t)b * D_ * D_;
    #pragma unroll
    for (int mt = 0; mt < 2; mt++)
        #pragma unroll
        for (int h = 0; h < 2; h++) {
            int d = m0 + warp_m * 32 + mt * 16 + quad + h * 8;
            #pragma unroll
            for (int nt = 0; nt < 8; nt++) {
                int e = n0 + warp_n * 64 + nt * 8 + tq * 2;
                size_t idx = base + (size_t)d * D_ + e;
                float2 w = *(const float2*)(Wc + idx);
                *(float2*)(Wn + idx) = make_float2(gC * w.x + acc[mt][nt][h*2+0],
                                                   gC * w.y + acc[mt][nt][h*2+1]);
            }
        }
}

// reads[t0+i, d] = gamma^i * sum_e r[i,e] W[d,e]  +  sum_j P[i,j] v[j,d]
__global__ __launch_bounds__(256) void k_reads(int t0, const float* __restrict__ Wc) {
    int b = blockIdx.z;
    const float* A  = g_out + ((size_t)b * T_ + t0) * D_;
    const float* Wb = Wc + (size_t)b * D_ * D_;
    const float* P  = g_P + (size_t)b * CB_ * CB_;
    __shared__ uint32_t As[16][136];
    __shared__ uint32_t Bs[16][136];
    int tid = threadIdx.x;
    int m0 = blockIdx.y * 128, n0 = blockIdx.x * 128;
    int warp = tid >> 5, lane = tid & 31;
    int warp_m = warp >> 1, warp_n = warp & 1;
    int quad = lane >> 2, tq = lane & 3;
    int r = tid >> 2, kc = (tid & 3) << 2;
    int ki = tid >> 4, cc = (tid & 15) << 3;
    float acc[2][8][4] = {};

    // phase 1: inter = r @ W^T (contract over e; both k-contiguous)
    for (int k0 = 0; k0 < D_; k0 += 16) {
        #pragma unroll
        for (int it = 0; it < 2; it++) {
            int rr = r + it * 64;
            float4 av = *(const float4*)(A + (size_t)(m0 + rr) * D_ + k0 + kc);
            As[kc+0][rr] = f2tf(av.x); As[kc+1][rr] = f2tf(av.y);
            As[kc+2][rr] = f2tf(av.z); As[kc+3][rr] = f2tf(av.w);
            float4 bv = *(const float4*)(Wb + (size_t)(n0 + rr) * D_ + k0 + kc);
            Bs[kc+0][rr] = f2tf(bv.x); Bs[kc+1][rr] = f2tf(bv.y);
            Bs[kc+2][rr] = f2tf(bv.z); Bs[kc+3][rr] = f2tf(bv.w);
        }
        __syncthreads();
        mma_block(As, Bs, acc, warp_m, warp_n, quad, tq);
        __syncthreads();
    }

    float lg = g_consts[0];
    #pragma unroll
    for (int mt = 0; mt < 2; mt++)
        #pragma unroll
        for (int h = 0; h < 2; h++) {
            int mi = m0 + warp_m * 32 + mt * 16 + quad + h * 8;
            float sc = __expf((float)mi * lg);
            #pragma unroll
            for (int nt = 0; nt < 8; nt++) {
                acc[mt][nt][h*2+0] *= sc;
                acc[mt][nt][h*2+1] *= sc;
            }
        }

    // phase 2: intra = P @ v (contract over j; P k-contig, v k-major)
    for (int k0 = 0; k0 < CB_; k0 += 16) {
        #pragma unroll
        for (int it = 0; it < 2; it++) {
            int rr = r + it * 64;
            float4 av = *(const float4*)(P + (size_t)(m0 + rr) * CB_ + k0 + kc);
            As[kc+0][rr] = f2tf(av.x); As[kc+1][rr] = f2tf(av.y);
            As[kc+2][rr] = f2tf(av.z); As[kc+3][rr] = f2tf(av.w);
        }
        const float* brow = g_v + ((size_t)b * T_ + t0 + k0 + ki) * D_ + n0 + cc;
        float4 b0 = *(const float4*)(brow);
        float4 b1 = *(const float4*)(brow + 4);
        Bs[ki][cc+0] = f2tf(b0.x); Bs[ki][cc+1] = f2tf(b0.y);
        Bs[ki][cc+2] = f2tf(b0.z); Bs[ki][cc+3] = f2tf(b0.w);
        Bs[ki][cc+4] = f2tf(b1.x); Bs[ki][cc+5] = f2tf(b1.y);
        Bs[ki][cc+6] = f2tf(b1.z); Bs[ki][cc+7] = f2tf(b1.w);
        __syncthreads();
        mma_block(As, Bs, acc, warp_m, warp_n, quad, tq);
        __syncthreads();
    }

    #pragma unroll
    for (int mt = 0; mt < 2; mt++)
        #pragma unroll
        for (int h = 0; h < 2; h++) {
            int mi = m0 + warp_m * 32 + mt * 16 + quad + h * 8;
            size_t row = ((size_t)b * T_ + t0 + mi) * D_;
            #pragma unroll
            for (int nt = 0; nt < 8; nt++) {
                int ni = n0 + warp_n * 64 + nt * 8 + tq * 2;
                *(float2*)(g_reads + row + ni) =
                    make_float2(acc[mt][nt][h*2+0], acc[mt][nt][h*2+1]);
            }
        }
}

// ---------------- launch ----------------------------------------------------
extern "C" void kernel_launch(void* const* d_in, const int* in_sizes, int n_in,
                              void* d_out, int out_size) {
    const float* x         = (const float*)d_in[0];
    const float* norm_w    = (const float*)d_in[1];
    const float* proj_w    = (const float*)d_in[2];
    const float* gate_w    = (const float*)d_in[3];
    const float* conv_w    = (const float*)d_in[4];
    const float* conv_b    = (const float*)d_in[5];
    const float* out_proj  = (const float*)d_in[6];
    const float* write_w   = (const float*)d_in[7];
    const float* read_w    = (const float*)d_in[8];
    const float* decay     = (const float*)d_in[9];
    const float* log_alpha = (const float*)d_in[10];
    float* out = (float*)d_out;

    float *p_rms, *p_val, *p_gate, *p_out, *p_v, *p_reads, *p_W;
    cudaGetSymbolAddress((void**)&p_rms,   g_rms);
    cudaGetSymbolAddress((void**)&p_val,   g_val);
    cudaGetSymbolAddress((void**)&p_gate,  g_gate);
    cudaGetSymbolAddress((void**)&p_out,   g_out);
    cudaGetSymbolAddress((void**)&p_v,     g_v);
    cudaGetSymbolAddress((void**)&p_reads, g_reads);
    cudaGetSymbolAddress((void**)&p_W,     g_W);
    float* p_W0 = p_W;
    float* p_W1 = p_W + (size_t)B_ * D_ * D_;

    k_consts<<<1, 1>>>(decay, log_alpha);
    k_rms<<<M_/8, 256>>>(x);

    // val = Xn @ proj^T ; gate = silu(Xn @ gate^T)
    k_gemm128<<<dim3(DI_/128, M_/128), 256>>>(x, proj_w, p_val, DI_, D_,
                                              p_rms, norm_w, 0, nullptr, nullptr);
    k_gemm128<<<dim3(DI_/128, M_/128), 256>>>(x, gate_w, p_gate, DI_, D_,
                                              p_rms, norm_w, 1, nullptr, nullptr);
    // h = silu(conv(val)+b) * gate   (into g_gate)
    k_conv<<<dim3(DI_/256, T_, B_), 256>>>(conv_w, conv_b);
    // out = h @ out_proj^T
    k_gemm128<<<dim3(D_/128, M_/128), 256>>>(p_gate, out_proj, p_out, D_, DI_,
                                             nullptr, nullptr, 0, nullptr, nullptr);
    // v = out @ write^T
    k_gemm128<<<dim3(D_/128, M_/128), 256>>>(p_out, write_w, p_v, D_, D_,
                                             nullptr, nullptr, 0, nullptr, nullptr);

    // chunked decay-linear-attention scan
    k_zeroW<<<(int)(((size_t)B_*D_*D_ + 1023) / 1024), 1024>>>();
    const float* Wc = p_W0;
    float* Wn = p_W1;
    for (int s = 0; s < NSTEP_; s++) {
        int t0 = s * CB_;
        k_pchunk <<<dim3(CB_/128, CB_/128, B_), 256>>>(t0);
        k_wupdate<<<dim3(D_/128,  D_/128,  B_), 256>>>(t0, Wc, Wn);
        k_reads  <<<dim3(D_/128,  CB_/128, B_), 256>>>(t0, Wc);
        float* tmp = (float*)Wc; Wc = Wn; Wn = tmp;
    }

    // final: y = x + out + alpha * (reads @ read^T)
    k_gemm128<<<dim3(D_/128, M_/128), 256>>>(p_reads, read_w, out, D_, D_,
                                             nullptr, nullptr, 2, x, p_out);
}